// round 6
// baseline (speedup 1.0000x reference)
#include <cuda_runtime.h>
#include <cstdint>

// ---------------------------------------------------------------------------
// Radon transform, 180 angles, 512x512, batch 2 — round 5 resubmit (infra
// failed twice; identical experiment so the R5 prediction stays testable).
//
// Confirmed model: radon kernel is L1tex-wavefront-bound; wavefronts/request ~
// (#image rows straddled by the 32 lanes) = 32*min(sin,cos). Dual-orientation
// (R4) cut that and won 158->129us.
//
// R5 changes:
//  1. build_padB via smem tile transpose (the old path did stride-512 scalar
//     reads: 10.4us, issue 11%). Coalesced loads + conflict-free smem.
//  2. r-split gridDim.z 2 -> 3: ~58 warps/SM to hide L1 latency.
// ---------------------------------------------------------------------------

#define W    512
#define NT   180
#define PW   520                 // cell row stride; 520*16B multiple of 128B
#define PH   517                 // rows used: index up to 516
#define NPIX (PW * PH)

__device__ float4 g_padA[NPIX];  // normal orientation
__device__ float4 g_padB[NPIX];  // transposed orientation

typedef unsigned long long u64;

__device__ __forceinline__ u64 pk2(float lo, float hi) {
    u64 r; asm("mov.b64 %0, {%1, %2};" : "=l"(r) : "f"(lo), "f"(hi)); return r;
}
__device__ __forceinline__ void unpk2(u64 v, float& lo, float& hi) {
    asm("mov.b64 {%0, %1}, %2;" : "=f"(lo), "=f"(hi) : "l"(v));
}
__device__ __forceinline__ u64 ffma2(u64 a, u64 b, u64 c) {
    u64 d; asm("fma.rn.f32x2 %0, %1, %2, %3;" : "=l"(d) : "l"(a), "l"(b), "l"(c)); return d;
}
__device__ __forceinline__ u64 fadd2(u64 a, u64 b) {
    u64 d; asm("add.rn.f32x2 %0, %1, %2;" : "=l"(d) : "l"(a), "l"(b)); return d;
}

// ---- normal-orientation build: coalesced direct ----------------------------
__global__ void build_padA(const float* __restrict__ x) {
    int idx = blockIdx.x * blockDim.x + threadIdx.x;
    if (idx >= NPIX) return;
    int ky = idx / PW;
    int kx = idx - ky * PW;
    int y  = ky - 2;
    int x0 = kx - 2;

    float a0 = 0.f, a1 = 0.f, b0 = 0.f, b1 = 0.f;
    if ((unsigned)y < W) {
        const float* r0 = x + y * W;
        const float* r1 = x + W * W + y * W;
        if ((unsigned)x0 < W)       { a0 = r0[x0];     a1 = r1[x0]; }
        if ((unsigned)(x0 + 1) < W) { b0 = r0[x0 + 1]; b1 = r1[x0 + 1]; }
    }
    g_padA[idx] = make_float4(a0, a1, b0, b1);
}

// ---- transposed-orientation build: smem tile transpose ----------------------
// padB cell (ky,kx): y = ky-2 = orig COLUMN, x0 = kx-2 = orig ROW.
// cell = (b0[x0][y], b1[x0][y], b0[x0+1][y], b1[x0+1][y]).
// Tile: kx in [TX,TX+32), ky in [TY,TY+32) -> orig rows [TX-2, TX+30] (33),
// orig cols [TY-2, TY+29] (32). smem[b][row 33][col 33] (33 stride: no conflicts).
__global__ __launch_bounds__(256) void build_padB_t(const float* __restrict__ x) {
    __shared__ float s[2][33][33];
    int TX = blockIdx.x * 32;            // kx tile base
    int TY = blockIdx.y * 32;            // ky tile base
    int lane = threadIdx.x;              // 0..31  (col / kx offset)
    int ty   = threadIdx.y;              // 0..7

    // load 33 rows x 32 cols, both batches
    for (int rr = ty; rr < 33; rr += 8) {
        int orow = TX - 2 + rr;          // orig row
        int ocol = TY - 2 + lane;        // orig col
        float v0 = 0.f, v1 = 0.f;
        if ((unsigned)orow < W && (unsigned)ocol < W) {
            v0 = x[orow * W + ocol];
            v1 = x[W * W + orow * W + ocol];
        }
        s[0][rr][lane] = v0;
        s[1][rr][lane] = v1;
    }
    __syncthreads();

    int kx = TX + lane;
    if (kx >= PW) return;
    for (int j = ty; j < 32; j += 8) {
        int ky = TY + j;
        if (ky >= PH) continue;
        // smem row index = lane (= x0 - (TX-2)), col index = j
        float4 e = make_float4(s[0][lane][j],     s[1][lane][j],
                               s[0][lane + 1][j], s[1][lane + 1][j]);
        g_padB[ky * PW + kx] = e;
    }
}

__global__ void zero_out(float* __restrict__ out, int n) {
    int i = blockIdx.x * blockDim.x + threadIdx.x;
    int stride = gridDim.x * blockDim.x;
    for (; i < n; i += stride) out[i] = 0.0f;
}

// ---- main kernel ------------------------------------------------------------
__global__ __launch_bounds__(128) void radon_kernel(float* __restrict__ out) {
    int c    = blockIdx.x * 128 + threadIdx.x;   // detector column 0..511
    int t    = blockIdx.y;                       // angle 0..179
    int part = blockIdx.z;                       // r-range third

    float th = (float)t * 0.017453292519943295f;
    float s  = sinf(th);                         // >= 0 for t in [0,180)
    float ct = cosf(th);

    float base_c = (float)(2 * c + 1) * (1.0f / 512.0f) - 1.0f;
    float ix0 = fmaf(-255.5f, s,  fmaf( 256.0f * ct, base_c, 255.5f));
    float iy0 = fmaf(-255.5f, ct, fmaf(-256.0f * s,  base_c, 255.5f));

    // clip r to where (ix,iy) in [-1,512]^2 ; +-1 step slop absorbed by pad
    float sx  = fmaxf(s, 1e-8f);
    float sy  = (fabsf(ct) < 1e-8f) ? ((ct < 0.f) ? -1e-8f : 1e-8f) : ct;
    float ivx = 1.0f / sx;
    float ivy = 1.0f / sy;
    float tx1 = (-1.0f  - ix0) * ivx;
    float tx2 = (512.0f - ix0) * ivx;
    float ty1 = (-1.0f  - iy0) * ivy;
    float ty2 = (512.0f - iy0) * ivy;
    float rminf = fmaxf(fmaxf(fminf(tx1, tx2), fminf(ty1, ty2)), 0.0f);
    float rmaxf = fminf(fminf(fmaxf(tx1, tx2), fmaxf(ty1, ty2)), 511.0f);
    rminf = fminf(rminf, 1024.0f);
    rmaxf = fmaxf(rmaxf, -2.0f);
    int rlo = (int)floorf(rminf);
    int rhi = (int)ceilf(rmaxf);

    // orientation select (uniform per block): minimize across-lane row slope.
    bool tr = s > fabsf(ct);
    float xc0, yc0, dxs, dys;
    const float4* __restrict__ base;
    if (!tr) { xc0 = ix0 + 2.0f; dxs = s;  yc0 = iy0 + 2.0f; dys = ct; base = g_padA; }
    else     { xc0 = iy0 + 2.0f; dxs = ct; yc0 = ix0 + 2.0f; dys = s;  base = g_padB; }

    // split r-range across gridDim.z = 3
    int len = rhi - rlo + 1;
    int per = (len + 2) / 3;
    if (per < 0) per = 0;
    int ra = rlo + part * per;
    int rb = ra + per - 1;
    if (rb > rhi) rb = rhi;

    const u64 M1 = pk2(-1.0f, -1.0f);
    u64 acc = pk2(0.0f, 0.0f);

#pragma unroll 4
    for (int r = ra; r <= rb; ++r) {
        float rf = (float)r;
        float px = fmaf(rf, dxs, xc0);
        float py = fmaf(rf, dys, yc0);
        int   x0 = (int)px;                      // coords >= 0: trunc == floor
        int   y0 = (int)py;
        float fx = px - (float)x0;
        float fy = py - (float)y0;

        int o = y0 * PW + x0;
        float4 va = __ldg(base + o);             // row y0:   b0@x, b1@x, b0@x+1, b1@x+1
        float4 vb = __ldg(base + o + PW);        // row y0+1

        u64 v00 = pk2(va.x, va.y);
        u64 v01 = pk2(va.z, va.w);
        u64 v10 = pk2(vb.x, vb.y);
        u64 v11 = pk2(vb.z, vb.w);
        u64 fxp = pk2(fx, fx);
        u64 fyp = pk2(fy, fy);

        u64 d0 = ffma2(v00, M1, v01);            // v01 - v00
        u64 l0 = ffma2(fxp, d0, v00);
        u64 d1 = ffma2(v10, M1, v11);            // v11 - v10
        u64 l1 = ffma2(fxp, d1, v10);
        u64 dl = ffma2(l0, M1, l1);              // l1 - l0
        u64 vv = ffma2(fyp, dl, l0);
        acc = fadd2(acc, vv);
    }

    float a0, a1;
    unpk2(acc, a0, a1);
    const float inv = 1.0f / 512.0f;
    int o0 = c * NT + t;
    atomicAdd(&out[o0],          a0 * inv);      // batch 0
    atomicAdd(&out[W * NT + o0], a1 * inv);      // batch 1
}

extern "C" void kernel_launch(void* const* d_in, const int* in_sizes, int n_in,
                              void* d_out, int out_size) {
    const float* x = (const float*)d_in[0];
    float* out = (float*)d_out;

    build_padA<<<(NPIX + 255) / 256, 256>>>(x);

    dim3 tgrid((PW + 31) / 32, (PH + 31) / 32);
    build_padB_t<<<tgrid, dim3(32, 8)>>>(x);

    zero_out<<<(out_size + 255) / 256, 256>>>(out, out_size);

    dim3 grid(W / 128, NT, 3);
    radon_kernel<<<grid, 128>>>(out);
}

// round 7
// speedup vs baseline: 1.3186x; 1.3186x over previous
#include <cuda_runtime.h>
#include <cstdint>

// ---------------------------------------------------------------------------
// Radon transform, 180 angles, 512x512, batch 2 — round 7.
//
// Model (confirmed R1/R6): radon kernel is L1-wavefront-bound; occupancy does
// NOT move it (z=3 at occ 62% == z=1 at occ 26%). Wavefronts per warp request
// = rows straddled x lines/row. New lever: 2D warp footprint.
//
// R7 changes:
//  * Warp = w x h tile over (detector column, r-phase), w*h=32, shape chosen
//    per angle from {32x1,16x2,8x4} x {normal,transposed} minimizing predicted
//    line count: rows ~ w*|dy/dc| + h*|dy/dr|.
//  * Block = 32 columns x 4 r-phases; phase partials reduced via smem.
//    z=1: no atomics, no zero_out.
//  * Warp-uniform r bounds (__reduce_min/max_sync); out-of-lane-range
//    iterations clamp coordinates into the zero pad bands (exact 0 result).
// ---------------------------------------------------------------------------

#define W    512
#define NT   180
#define PW   520                 // cell row stride; 520*16B multiple of 128B
#define PH   517
#define NPIX (PW * PH)

__device__ float4 g_padA[NPIX];  // normal orientation
__device__ float4 g_padB[NPIX];  // transposed orientation

typedef unsigned long long u64;

__device__ __forceinline__ u64 pk2(float lo, float hi) {
    u64 r; asm("mov.b64 %0, {%1, %2};" : "=l"(r) : "f"(lo), "f"(hi)); return r;
}
__device__ __forceinline__ void unpk2(u64 v, float& lo, float& hi) {
    asm("mov.b64 {%0, %1}, %2;" : "=f"(lo), "=f"(hi) : "l"(v));
}
__device__ __forceinline__ u64 ffma2(u64 a, u64 b, u64 c) {
    u64 d; asm("fma.rn.f32x2 %0, %1, %2, %3;" : "=l"(d) : "l"(a), "l"(b), "l"(c)); return d;
}
__device__ __forceinline__ u64 fadd2(u64 a, u64 b) {
    u64 d; asm("add.rn.f32x2 %0, %1, %2;" : "=l"(d) : "l"(a), "l"(b)); return d;
}

// ---- normal-orientation build: coalesced direct ----------------------------
__global__ void build_padA(const float* __restrict__ x) {
    int idx = blockIdx.x * blockDim.x + threadIdx.x;
    if (idx >= NPIX) return;
    int ky = idx / PW;
    int kx = idx - ky * PW;
    int y  = ky - 2;
    int x0 = kx - 2;

    float a0 = 0.f, a1 = 0.f, b0 = 0.f, b1 = 0.f;
    if ((unsigned)y < W) {
        const float* r0 = x + y * W;
        const float* r1 = x + W * W + y * W;
        if ((unsigned)x0 < W)       { a0 = r0[x0];     a1 = r1[x0]; }
        if ((unsigned)(x0 + 1) < W) { b0 = r0[x0 + 1]; b1 = r1[x0 + 1]; }
    }
    g_padA[idx] = make_float4(a0, a1, b0, b1);
}

// ---- transposed-orientation build: smem tile transpose ----------------------
__global__ __launch_bounds__(256) void build_padB_t(const float* __restrict__ x) {
    __shared__ float s[2][33][33];
    int TX = blockIdx.x * 32;
    int TY = blockIdx.y * 32;
    int lane = threadIdx.x;
    int ty   = threadIdx.y;

    for (int rr = ty; rr < 33; rr += 8) {
        int orow = TX - 2 + rr;
        int ocol = TY - 2 + lane;
        float v0 = 0.f, v1 = 0.f;
        if ((unsigned)orow < W && (unsigned)ocol < W) {
            v0 = x[orow * W + ocol];
            v1 = x[W * W + orow * W + ocol];
        }
        s[0][rr][lane] = v0;
        s[1][rr][lane] = v1;
    }
    __syncthreads();

    int kx = TX + lane;
    if (kx >= PW) return;
    for (int j = ty; j < 32; j += 8) {
        int ky = TY + j;
        if (ky >= PH) continue;
        float4 e = make_float4(s[0][lane][j],     s[1][lane][j],
                               s[0][lane + 1][j], s[1][lane + 1][j]);
        g_padB[ky * PW + kx] = e;
    }
}

// ---- main kernel ------------------------------------------------------------
__global__ __launch_bounds__(128) void radon_kernel(float* __restrict__ out) {
    __shared__ float2 red[4][32];

    int tid  = threadIdx.x;
    int lane = tid & 31;
    int wid  = tid >> 5;
    int t    = blockIdx.y;

    float th = (float)t * 0.017453292519943295f;
    float s  = sinf(th);                         // >= 0 for t in [0,180)
    float ct = cosf(th);
    float act = fabsf(ct);

    // ---- shape + orientation selection (uniform per block) ----
    // a = |dy/dc|, b = |dy/dr|, cx = |dx/dc| in each orientation.
    float bestc = 1e30f; int best_lw = 5; int best_tr = 0;
#pragma unroll
    for (int o = 0; o < 2; o++) {
        float a  = o ? act : s;
        float b  = o ? s   : act;
        float cx = o ? s   : act;
#pragma unroll
        for (int lw = 3; lw <= 5; lw++) {
            float wf = (float)(1 << lw);
            float hf = 32.0f / wf;
            float cost = (wf * a + hf * b + 2.0f) * (1.0f + wf * cx * (1.0f / 16.0f));
            if (cost < bestc) { bestc = cost; best_lw = lw; best_tr = o; }
        }
    }
    int lw     = best_lw;
    int w_     = 1 << lw;
    int h_     = 32 >> lw;
    int cgbits = 5 - lw;                         // log2(col groups)
    int cl  = lane & (w_ - 1);
    int rp  = lane >> lw;
    int col_group   = wid & ((1 << cgbits) - 1);
    int phase_group = wid >> cgbits;
    int phase   = phase_group * h_ + rp;         // 0..3
    int c_local = col_group * w_ + cl;           // 0..31
    int c = blockIdx.x * 32 + c_local;

    float base_c = (float)(2 * c + 1) * (1.0f / 512.0f) - 1.0f;
    float ix0 = fmaf(-255.5f, s,  fmaf( 256.0f * ct, base_c, 255.5f));
    float iy0 = fmaf(-255.5f, ct, fmaf(-256.0f * s,  base_c, 255.5f));

    // clip r to where (ix,iy) in [-1,512]^2
    float sx  = fmaxf(s, 1e-8f);
    float sy  = (act < 1e-8f) ? ((ct < 0.f) ? -1e-8f : 1e-8f) : ct;
    float ivx = 1.0f / sx;
    float ivy = 1.0f / sy;
    float tx1 = (-1.0f  - ix0) * ivx;
    float tx2 = (512.0f - ix0) * ivx;
    float ty1 = (-1.0f  - iy0) * ivy;
    float ty2 = (512.0f - iy0) * ivy;
    float rminf = fmaxf(fmaxf(fminf(tx1, tx2), fminf(ty1, ty2)), 0.0f);
    float rmaxf = fminf(fminf(fmaxf(tx1, tx2), fmaxf(ty1, ty2)), 511.0f);
    rminf = fminf(rminf, 1024.0f);
    rmaxf = fmaxf(rmaxf, -2.0f);
    int ra = (int)floorf(rminf);
    int rb = (int)ceilf(rmaxf);

    // warp-uniform bounds; lane-OOB iterations read guaranteed-zero pad cells
    int ra_w = __reduce_min_sync(0xffffffffu, ra);
    int rb_w = __reduce_max_sync(0xffffffffu, rb);

    float xc0, yc0, dxs, dys;
    const float4* __restrict__ base;
    if (!best_tr) { xc0 = ix0 + 2.0f; dxs = s;  yc0 = iy0 + 2.0f; dys = ct; base = g_padA; }
    else          { xc0 = iy0 + 2.0f; dxs = ct; yc0 = ix0 + 2.0f; dys = s;  base = g_padB; }

    const u64 M1 = pk2(-1.0f, -1.0f);
    u64 acc = pk2(0.0f, 0.0f);

#pragma unroll 4
    for (int r = ra_w + phase; r <= rb_w; r += 4) {
        float rf = (float)r;
        float px = fmaf(rf, dxs, xc0);
        float py = fmaf(rf, dys, yc0);
        px = fminf(fmaxf(px, 0.0f), 516.0f);     // clamp into zero pad bands
        py = fminf(fmaxf(py, 0.0f), 515.0f);
        int   x0 = (int)px;                      // >= 0: trunc == floor
        int   y0 = (int)py;
        float fx = px - (float)x0;
        float fy = py - (float)y0;

        int o = y0 * PW + x0;
        float4 va = __ldg(base + o);             // row y0
        float4 vb = __ldg(base + o + PW);        // row y0+1

        u64 v00 = pk2(va.x, va.y);
        u64 v01 = pk2(va.z, va.w);
        u64 v10 = pk2(vb.x, vb.y);
        u64 v11 = pk2(vb.z, vb.w);
        u64 fxp = pk2(fx, fx);
        u64 fyp = pk2(fy, fy);

        u64 d0 = ffma2(v00, M1, v01);
        u64 l0 = ffma2(fxp, d0, v00);
        u64 d1 = ffma2(v10, M1, v11);
        u64 l1 = ffma2(fxp, d1, v10);
        u64 dl = ffma2(l0, M1, l1);
        u64 vv = ffma2(fyp, dl, l0);
        acc = fadd2(acc, vv);
    }

    float a0, a1;
    unpk2(acc, a0, a1);
    red[phase][c_local] = make_float2(a0, a1);
    __syncthreads();

    if (tid < 32) {
        float2 r0 = red[0][tid], r1 = red[1][tid], r2 = red[2][tid], r3 = red[3][tid];
        float sa = (r0.x + r1.x) + (r2.x + r3.x);
        float sb = (r0.y + r1.y) + (r2.y + r3.y);
        const float inv = 1.0f / 512.0f;
        int c2 = blockIdx.x * 32 + tid;
        int o0 = c2 * NT + t;
        out[o0]           = sa * inv;            // batch 0
        out[W * NT + o0]  = sb * inv;            // batch 1
    }
}

extern "C" void kernel_launch(void* const* d_in, const int* in_sizes, int n_in,
                              void* d_out, int out_size) {
    const float* x = (const float*)d_in[0];
    float* out = (float*)d_out;

    build_padA<<<(NPIX + 255) / 256, 256>>>(x);

    dim3 tgrid((PW + 31) / 32, (PH + 31) / 32);
    build_padB_t<<<tgrid, dim3(32, 8)>>>(x);

    dim3 grid(W / 32, NT);
    radon_kernel<<<grid, 128>>>(out);
}

// round 8
// speedup vs baseline: 1.9088x; 1.4476x over previous
#include <cuda_runtime.h>
#include <cuda_fp16.h>
#include <cstdint>

// ---------------------------------------------------------------------------
// Radon transform, 180 angles, 512x512, batch 2 — round 8.
//
// Confirmed: radon is L1-wavefront-bound; wavefronts = 2 requests/sample x
// footprint lines; occupancy & footprint-shape tweaks are ~neutral.
//
// R8 lever: fp16 "full corner" cells. cell(y,x) = 16B = 8 halves:
//   (v00, v01, v10, v11), each half2(batch0, batch1), covering BOTH rows and
//   BOTH x-neighbors. ONE LDG.128 per bilinear sample (was two), same 16B/cell
//   x-stride -> ~half the L1 wavefronts. Lerp still in fp32 (packed f32x2);
//   only input quantization (fp16, ~1.4e-4 RMS) enters the error.
// ---------------------------------------------------------------------------

#define W    512
#define NT   180
#define PW   520                 // cell row stride; 520*16B multiple of 128B
#define PH   517
#define NPIX (PW * PH)

__device__ uint4 g_padA[NPIX];   // normal orientation  (16B corner cells)
__device__ uint4 g_padB[NPIX];   // transposed orientation

typedef unsigned long long u64;

__device__ __forceinline__ u64 pk2(float lo, float hi) {
    u64 r; asm("mov.b64 %0, {%1, %2};" : "=l"(r) : "f"(lo), "f"(hi)); return r;
}
__device__ __forceinline__ void unpk2(u64 v, float& lo, float& hi) {
    asm("mov.b64 {%0, %1}, %2;" : "=f"(lo), "=f"(hi) : "l"(v));
}
__device__ __forceinline__ u64 ffma2(u64 a, u64 b, u64 c) {
    u64 d; asm("fma.rn.f32x2 %0, %1, %2, %3;" : "=l"(d) : "l"(a), "l"(b), "l"(c)); return d;
}
__device__ __forceinline__ u64 fadd2(u64 a, u64 b) {
    u64 d; asm("add.rn.f32x2 %0, %1, %2;" : "=l"(d) : "l"(a), "l"(b)); return d;
}
__device__ __forceinline__ u64 h2f2(uint32_t h) {        // half2 -> packed f32x2
    __half2 hh = *reinterpret_cast<__half2*>(&h);
    float2 f = __half22float2(hh);
    return pk2(f.x, f.y);
}

// ---- normal-orientation build ----------------------------------------------
// cell(ky,kx): y=ky-2, x=kx-2; corners (y,x),(y,x+1),(y+1,x),(y+1,x+1), both
// batches, packed half2(b0,b1) each. Adjacent threads -> adjacent x: coalesced.
__global__ void build_padA(const float* __restrict__ x) {
    int idx = blockIdx.x * blockDim.x + threadIdx.x;
    if (idx >= NPIX) return;
    int ky = idx / PW;
    int kx = idx - ky * PW;
    int y  = ky - 2;
    int x0 = kx - 2;

    auto val = [&](int b, int r, int c) -> float {
        if ((unsigned)r < W && (unsigned)c < W)
            return x[b * (W * W) + r * W + c];
        return 0.0f;
    };
    __half2 h00 = __floats2half2_rn(val(0, y,     x0),     val(1, y,     x0));
    __half2 h01 = __floats2half2_rn(val(0, y,     x0 + 1), val(1, y,     x0 + 1));
    __half2 h10 = __floats2half2_rn(val(0, y + 1, x0),     val(1, y + 1, x0));
    __half2 h11 = __floats2half2_rn(val(0, y + 1, x0 + 1), val(1, y + 1, x0 + 1));
    uint4 cell;
    cell.x = *reinterpret_cast<uint32_t*>(&h00);
    cell.y = *reinterpret_cast<uint32_t*>(&h01);
    cell.z = *reinterpret_cast<uint32_t*>(&h10);
    cell.w = *reinterpret_cast<uint32_t*>(&h11);
    g_padA[idx] = cell;
}

// ---- transposed-orientation build: smem tile transpose ----------------------
// padB value at (x,y) = img[x][y]. Cell(ky,kx), x0=kx-2, y0=ky-2 needs
// img rows x0,x0+1 and cols y0,y0+1. Tile loads 33 rows x 33 cols.
__global__ __launch_bounds__(256) void build_padB_t(const float* __restrict__ x) {
    __shared__ float s[2][33][35];
    int TX = blockIdx.x * 32;            // kx tile base (orig rows)
    int TY = blockIdx.y * 32;            // ky tile base (orig cols)
    int lane = threadIdx.x;
    int ty   = threadIdx.y;

    for (int rr = ty; rr < 33; rr += 8) {
        int orow = TX - 2 + rr;
        for (int cc = lane; cc < 33; cc += 32) {
            int ocol = TY - 2 + cc;
            float v0 = 0.f, v1 = 0.f;
            if ((unsigned)orow < W && (unsigned)ocol < W) {
                v0 = x[orow * W + ocol];
                v1 = x[W * W + orow * W + ocol];
            }
            s[0][rr][cc] = v0;
            s[1][rr][cc] = v1;
        }
    }
    __syncthreads();

    int kx = TX + lane;
    if (kx >= PW) return;
    for (int j = ty; j < 32; j += 8) {
        int ky = TY + j;
        if (ky >= PH) continue;
        // smem: row index = lane (= x0 offset), col index = j (= y0 offset)
        __half2 h00 = __floats2half2_rn(s[0][lane][j],         s[1][lane][j]);
        __half2 h01 = __floats2half2_rn(s[0][lane + 1][j],     s[1][lane + 1][j]);
        __half2 h10 = __floats2half2_rn(s[0][lane][j + 1],     s[1][lane][j + 1]);
        __half2 h11 = __floats2half2_rn(s[0][lane + 1][j + 1], s[1][lane + 1][j + 1]);
        uint4 cell;
        cell.x = *reinterpret_cast<uint32_t*>(&h00);
        cell.y = *reinterpret_cast<uint32_t*>(&h01);
        cell.z = *reinterpret_cast<uint32_t*>(&h10);
        cell.w = *reinterpret_cast<uint32_t*>(&h11);
        g_padB[ky * PW + kx] = cell;
    }
}

// ---- main kernel ------------------------------------------------------------
__global__ __launch_bounds__(128) void radon_kernel(float* __restrict__ out) {
    __shared__ float2 red[4][32];

    int tid  = threadIdx.x;
    int lane = tid & 31;
    int wid  = tid >> 5;
    int t    = blockIdx.y;

    float th = (float)t * 0.017453292519943295f;
    float s  = sinf(th);                         // >= 0 for t in [0,180)
    float ct = cosf(th);
    float act = fabsf(ct);

    // shape + orientation selection (uniform per block)
    float bestc = 1e30f; int best_lw = 5; int best_tr = 0;
#pragma unroll
    for (int o = 0; o < 2; o++) {
        float a  = o ? act : s;
        float b  = o ? s   : act;
        float cx = o ? s   : act;
#pragma unroll
        for (int lw = 3; lw <= 5; lw++) {
            float wf = (float)(1 << lw);
            float hf = 32.0f / wf;
            float cost = (wf * a + hf * b + 2.0f) * (1.0f + wf * cx * (1.0f / 16.0f));
            if (cost < bestc) { bestc = cost; best_lw = lw; best_tr = o; }
        }
    }
    int lw     = best_lw;
    int w_     = 1 << lw;
    int h_     = 32 >> lw;
    int cgbits = 5 - lw;
    int cl  = lane & (w_ - 1);
    int rp  = lane >> lw;
    int col_group   = wid & ((1 << cgbits) - 1);
    int phase_group = wid >> cgbits;
    int phase   = phase_group * h_ + rp;         // 0..3
    int c_local = col_group * w_ + cl;           // 0..31
    int c = blockIdx.x * 32 + c_local;

    float base_c = (float)(2 * c + 1) * (1.0f / 512.0f) - 1.0f;
    float ix0 = fmaf(-255.5f, s,  fmaf( 256.0f * ct, base_c, 255.5f));
    float iy0 = fmaf(-255.5f, ct, fmaf(-256.0f * s,  base_c, 255.5f));

    // clip r to where (ix,iy) in [-1,512]^2
    float sx  = fmaxf(s, 1e-8f);
    float sy  = (act < 1e-8f) ? ((ct < 0.f) ? -1e-8f : 1e-8f) : ct;
    float ivx = 1.0f / sx;
    float ivy = 1.0f / sy;
    float tx1 = (-1.0f  - ix0) * ivx;
    float tx2 = (512.0f - ix0) * ivx;
    float ty1 = (-1.0f  - iy0) * ivy;
    float ty2 = (512.0f - iy0) * ivy;
    float rminf = fmaxf(fmaxf(fminf(tx1, tx2), fminf(ty1, ty2)), 0.0f);
    float rmaxf = fminf(fminf(fmaxf(tx1, tx2), fmaxf(ty1, ty2)), 511.0f);
    rminf = fminf(rminf, 1024.0f);
    rmaxf = fmaxf(rmaxf, -2.0f);
    int ra = (int)floorf(rminf);
    int rb = (int)ceilf(rmaxf);

    int ra_w = __reduce_min_sync(0xffffffffu, ra);
    int rb_w = __reduce_max_sync(0xffffffffu, rb);

    float xc0, yc0, dxs, dys;
    const uint4* __restrict__ base;
    if (!best_tr) { xc0 = ix0 + 2.0f; dxs = s;  yc0 = iy0 + 2.0f; dys = ct; base = g_padA; }
    else          { xc0 = iy0 + 2.0f; dxs = ct; yc0 = ix0 + 2.0f; dys = s;  base = g_padB; }

    const u64 M1 = pk2(-1.0f, -1.0f);
    u64 acc = pk2(0.0f, 0.0f);

#pragma unroll 4
    for (int r = ra_w + phase; r <= rb_w; r += 4) {
        float rf = (float)r;
        float px = fmaf(rf, dxs, xc0);
        float py = fmaf(rf, dys, yc0);
        px = fminf(fmaxf(px, 0.0f), 516.0f);     // clamp into zero pad bands
        py = fminf(fmaxf(py, 0.0f), 515.0f);
        int   x0 = (int)px;                      // >= 0: trunc == floor
        int   y0 = (int)py;
        float fx = px - (float)x0;
        float fy = py - (float)y0;

        uint4 cell = __ldg(base + (y0 * PW + x0));   // ONE LDG.128: all 4 corners

        u64 v00 = h2f2(cell.x);
        u64 v01 = h2f2(cell.y);
        u64 v10 = h2f2(cell.z);
        u64 v11 = h2f2(cell.w);
        u64 fxp = pk2(fx, fx);
        u64 fyp = pk2(fy, fy);

        u64 d0 = ffma2(v00, M1, v01);            // v01 - v00
        u64 l0 = ffma2(fxp, d0, v00);
        u64 d1 = ffma2(v10, M1, v11);            // v11 - v10
        u64 l1 = ffma2(fxp, d1, v10);
        u64 dl = ffma2(l0, M1, l1);              // l1 - l0
        u64 vv = ffma2(fyp, dl, l0);
        acc = fadd2(acc, vv);
    }

    float a0, a1;
    unpk2(acc, a0, a1);
    red[phase][c_local] = make_float2(a0, a1);
    __syncthreads();

    if (tid < 32) {
        float2 r0 = red[0][tid], r1 = red[1][tid], r2 = red[2][tid], r3 = red[3][tid];
        float sa = (r0.x + r1.x) + (r2.x + r3.x);
        float sb = (r0.y + r1.y) + (r2.y + r3.y);
        const float inv = 1.0f / 512.0f;
        int c2 = blockIdx.x * 32 + tid;
        int o0 = c2 * NT + t;
        out[o0]           = sa * inv;            // batch 0
        out[W * NT + o0]  = sb * inv;            // batch 1
    }
}

extern "C" void kernel_launch(void* const* d_in, const int* in_sizes, int n_in,
                              void* d_out, int out_size) {
    const float* x = (const float*)d_in[0];
    float* out = (float*)d_out;

    build_padA<<<(NPIX + 255) / 256, 256>>>(x);

    dim3 tgrid((PW + 31) / 32, (PH + 31) / 32);
    build_padB_t<<<tgrid, dim3(32, 8)>>>(x);

    dim3 grid(W / 32, NT);
    radon_kernel<<<grid, 128>>>(out);
}

// round 9
// speedup vs baseline: 2.0244x; 1.0606x over previous
#include <cuda_runtime.h>
#include <cuda_fp16.h>
#include <cstdint>

// ---------------------------------------------------------------------------
// Radon transform, 180 angles, 512x512, batch 2 — round 9.
//
// R8 confirmed: fp16 corner cells (one LDG.128/sample) -> 89us. Now ~half
// issue-bound. R9 trims the inner loop:
//  * per-lane integer r clamp to [ra-1, rb+1] (2 IMNMX) replaces 4 float
//    coordinate clamps; clamped samples are EXACTLY zero (all-zero corners)
//    because the binding coordinate is past the +-1/512 boundary. Pad band
//    widened 2 -> 4 so clamped lookups stay in-bounds.
//  * x-lerp in native half2 (HSUB2/HFMA2), only l0/l1 converted to f32;
//    y-lerp + accumulation stay fp32 (packed f32x2). 2 accumulators.
// ---------------------------------------------------------------------------

#define W    512
#define NT   180
#define PW   520                 // cells per row; 520*16B multiple of 128B
#define PH   520
#define NPIX (PW * PH)
#define PAD  4

__device__ uint4 g_padA[NPIX];   // normal orientation  (16B corner cells)
__device__ uint4 g_padB[NPIX];   // transposed orientation

typedef unsigned long long u64;

__device__ __forceinline__ u64 pk2(float lo, float hi) {
    u64 r; asm("mov.b64 %0, {%1, %2};" : "=l"(r) : "f"(lo), "f"(hi)); return r;
}
__device__ __forceinline__ void unpk2(u64 v, float& lo, float& hi) {
    asm("mov.b64 {%0, %1}, %2;" : "=f"(lo), "=f"(hi) : "l"(v));
}
__device__ __forceinline__ u64 ffma2(u64 a, u64 b, u64 c) {
    u64 d; asm("fma.rn.f32x2 %0, %1, %2, %3;" : "=l"(d) : "l"(a), "l"(b), "l"(c)); return d;
}
__device__ __forceinline__ u64 fadd2(u64 a, u64 b) {
    u64 d; asm("add.rn.f32x2 %0, %1, %2;" : "=l"(d) : "l"(a), "l"(b)); return d;
}
__device__ __forceinline__ u64 h2f2(__half2 h) {         // half2 -> packed f32x2
    float2 f = __half22float2(h);
    return pk2(f.x, f.y);
}

// ---- normal-orientation build ----------------------------------------------
__global__ void build_padA(const float* __restrict__ x) {
    int idx = blockIdx.x * blockDim.x + threadIdx.x;
    if (idx >= NPIX) return;
    int ky = idx / PW;
    int kx = idx - ky * PW;
    int y  = ky - PAD;
    int x0 = kx - PAD;

    auto val = [&](int b, int r, int c) -> float {
        if ((unsigned)r < W && (unsigned)c < W)
            return x[b * (W * W) + r * W + c];
        return 0.0f;
    };
    __half2 h00 = __floats2half2_rn(val(0, y,     x0),     val(1, y,     x0));
    __half2 h01 = __floats2half2_rn(val(0, y,     x0 + 1), val(1, y,     x0 + 1));
    __half2 h10 = __floats2half2_rn(val(0, y + 1, x0),     val(1, y + 1, x0));
    __half2 h11 = __floats2half2_rn(val(0, y + 1, x0 + 1), val(1, y + 1, x0 + 1));
    uint4 cell;
    cell.x = *reinterpret_cast<uint32_t*>(&h00);
    cell.y = *reinterpret_cast<uint32_t*>(&h01);
    cell.z = *reinterpret_cast<uint32_t*>(&h10);
    cell.w = *reinterpret_cast<uint32_t*>(&h11);
    g_padA[idx] = cell;
}

// ---- transposed-orientation build: smem tile transpose ----------------------
__global__ __launch_bounds__(256) void build_padB_t(const float* __restrict__ x) {
    __shared__ float s[2][33][35];
    int TX = blockIdx.x * 32;            // kx tile base (orig rows)
    int TY = blockIdx.y * 32;            // ky tile base (orig cols)
    int lane = threadIdx.x;
    int ty   = threadIdx.y;

    for (int rr = ty; rr < 33; rr += 8) {
        int orow = TX - PAD + rr;
        for (int cc = lane; cc < 33; cc += 32) {
            int ocol = TY - PAD + cc;
            float v0 = 0.f, v1 = 0.f;
            if ((unsigned)orow < W && (unsigned)ocol < W) {
                v0 = x[orow * W + ocol];
                v1 = x[W * W + orow * W + ocol];
            }
            s[0][rr][cc] = v0;
            s[1][rr][cc] = v1;
        }
    }
    __syncthreads();

    int kx = TX + lane;
    if (kx >= PW) return;
    for (int j = ty; j < 32; j += 8) {
        int ky = TY + j;
        if (ky >= PH) continue;
        __half2 h00 = __floats2half2_rn(s[0][lane][j],         s[1][lane][j]);
        __half2 h01 = __floats2half2_rn(s[0][lane + 1][j],     s[1][lane + 1][j]);
        __half2 h10 = __floats2half2_rn(s[0][lane][j + 1],     s[1][lane][j + 1]);
        __half2 h11 = __floats2half2_rn(s[0][lane + 1][j + 1], s[1][lane + 1][j + 1]);
        uint4 cell;
        cell.x = *reinterpret_cast<uint32_t*>(&h00);
        cell.y = *reinterpret_cast<uint32_t*>(&h01);
        cell.z = *reinterpret_cast<uint32_t*>(&h10);
        cell.w = *reinterpret_cast<uint32_t*>(&h11);
        g_padB[ky * PW + kx] = cell;
    }
}

// ---- main kernel ------------------------------------------------------------
__global__ __launch_bounds__(128) void radon_kernel(float* __restrict__ out) {
    __shared__ float2 red[4][32];

    int tid  = threadIdx.x;
    int lane = tid & 31;
    int wid  = tid >> 5;
    int t    = blockIdx.y;

    float th = (float)t * 0.017453292519943295f;
    float s  = sinf(th);                         // >= 0 for t in [0,180)
    float ct = cosf(th);
    float act = fabsf(ct);

    // shape + orientation selection (uniform per block)
    float bestc = 1e30f; int best_lw = 5; int best_tr = 0;
#pragma unroll
    for (int o = 0; o < 2; o++) {
        float a  = o ? act : s;
        float b  = o ? s   : act;
        float cx = o ? s   : act;
#pragma unroll
        for (int lw = 3; lw <= 5; lw++) {
            float wf = (float)(1 << lw);
            float hf = 32.0f / wf;
            float cost = (wf * a + hf * b + 2.0f) * (1.0f + wf * cx * (1.0f / 16.0f));
            if (cost < bestc) { bestc = cost; best_lw = lw; best_tr = o; }
        }
    }
    int lw     = best_lw;
    int w_     = 1 << lw;
    int h_     = 32 >> lw;
    int cgbits = 5 - lw;
    int cl  = lane & (w_ - 1);
    int rp  = lane >> lw;
    int col_group   = wid & ((1 << cgbits) - 1);
    int phase_group = wid >> cgbits;
    int phase   = phase_group * h_ + rp;         // 0..3
    int c_local = col_group * w_ + cl;           // 0..31
    int c = blockIdx.x * 32 + c_local;

    float base_c = (float)(2 * c + 1) * (1.0f / 512.0f) - 1.0f;
    float ix0 = fmaf(-255.5f, s,  fmaf( 256.0f * ct, base_c, 255.5f));
    float iy0 = fmaf(-255.5f, ct, fmaf(-256.0f * s,  base_c, 255.5f));

    // clip r to where (ix,iy) in [-1,512]^2. Every ray passes within 256
    // pixels of the image center, so [rminf, rmaxf] always contains 255.5.
    float sx  = fmaxf(s, 1e-8f);
    float sy  = (act < 1e-8f) ? ((ct < 0.f) ? -1e-8f : 1e-8f) : ct;
    float ivx = 1.0f / sx;
    float ivy = 1.0f / sy;
    float tx1 = (-1.0f  - ix0) * ivx;
    float tx2 = (512.0f - ix0) * ivx;
    float ty1 = (-1.0f  - iy0) * ivy;
    float ty2 = (512.0f - iy0) * ivy;
    float rminf = fmaxf(fmaxf(fminf(tx1, tx2), fminf(ty1, ty2)), 0.0f);
    float rmaxf = fminf(fminf(fmaxf(tx1, tx2), fmaxf(ty1, ty2)), 511.0f);
    int ra = (int)floorf(rminf);
    int rb = (int)ceilf(rmaxf);

    int ra_w = __reduce_min_sync(0xffffffffu, ra);
    int rb_w = __reduce_max_sync(0xffffffffu, rb);
    int ra1 = ra - 1;                    // samples at ra-1 / rb+1 are EXACTLY 0
    int rb1 = rb + 1;                    // (binding coordinate past the edge)

    float xc0, yc0, dxs, dys;
    const uint4* __restrict__ base;
    if (!best_tr) { xc0 = ix0 + (float)PAD; dxs = s;  yc0 = iy0 + (float)PAD; dys = ct; base = g_padA; }
    else          { xc0 = iy0 + (float)PAD; dxs = ct; yc0 = ix0 + (float)PAD; dys = s;  base = g_padB; }

    const u64 M1 = pk2(-1.0f, -1.0f);
    u64 acc0 = pk2(0.0f, 0.0f);
    u64 acc1 = pk2(0.0f, 0.0f);
    int toggle = 0;

#pragma unroll 8
    for (int r = ra_w + phase; r <= rb_w; r += 4) {
        int rr = min(max(r, ra1), rb1);          // per-lane clamp: OOB -> zero cell
        float rf = (float)rr;
        float px = fmaf(rf, dxs, xc0);           // in [1, 518] after clamp
        float py = fmaf(rf, dys, yc0);
        int   x0 = (int)px;                      // > 0: trunc == floor
        int   y0 = (int)py;
        float fx = px - (float)x0;
        float fy = py - (float)y0;

        uint4 cell = __ldg(base + (y0 * PW + x0));   // ONE LDG.128: all 4 corners

        __half2 v00 = *reinterpret_cast<__half2*>(&cell.x);
        __half2 v01 = *reinterpret_cast<__half2*>(&cell.y);
        __half2 v10 = *reinterpret_cast<__half2*>(&cell.z);
        __half2 v11 = *reinterpret_cast<__half2*>(&cell.w);

        __half2 fxh = __floats2half2_rn(fx, fx); // one F2FP
        __half2 l0h = __hfma2(fxh, __hsub2(v01, v00), v00);  // x-lerp row y0
        __half2 l1h = __hfma2(fxh, __hsub2(v11, v10), v10);  // x-lerp row y0+1

        u64 l0 = h2f2(l0h);
        u64 l1 = h2f2(l1h);
        u64 fyp = pk2(fy, fy);
        u64 dl = ffma2(l0, M1, l1);              // l1 - l0
        u64 vv = ffma2(fyp, dl, l0);             // y-lerp in fp32
        if (toggle) acc1 = fadd2(acc1, vv); else acc0 = fadd2(acc0, vv);
        toggle ^= 1;
    }
    u64 acc = fadd2(acc0, acc1);

    float a0, a1;
    unpk2(acc, a0, a1);
    red[phase][c_local] = make_float2(a0, a1);
    __syncthreads();

    if (tid < 32) {
        float2 r0 = red[0][tid], r1 = red[1][tid], r2 = red[2][tid], r3 = red[3][tid];
        float sa = (r0.x + r1.x) + (r2.x + r3.x);
        float sb = (r0.y + r1.y) + (r2.y + r3.y);
        const float inv = 1.0f / 512.0f;
        int c2 = blockIdx.x * 32 + tid;
        int o0 = c2 * NT + t;
        out[o0]           = sa * inv;            // batch 0
        out[W * NT + o0]  = sb * inv;            // batch 1
    }
}

extern "C" void kernel_launch(void* const* d_in, const int* in_sizes, int n_in,
                              void* d_out, int out_size) {
    const float* x = (const float*)d_in[0];
    float* out = (float*)d_out;

    build_padA<<<(NPIX + 255) / 256, 256>>>(x);

    dim3 tgrid((PW + 31) / 32, (PH + 31) / 32);
    build_padB_t<<<tgrid, dim3(32, 8)>>>(x);

    dim3 grid(W / 32, NT);
    radon_kernel<<<grid, 128>>>(out);
}

// round 11
// speedup vs baseline: 2.0717x; 1.0234x over previous
#include <cuda_runtime.h>
#include <cuda_fp16.h>
#include <cstdint>

// ---------------------------------------------------------------------------
// Radon transform, 180 angles, 512x512, batch 2 — round 11.
//
// R10 failed (rel_err 3.5e-2) after changing floor-trick + loop + fy-half at
// once. R11 rebases on R9 (84us, passed) and applies only separable changes:
//  1. fused build kernel (z selects orientation; outputs identical to R9).
//  2. fy-lerp in half2 (bounded: <=3 half roundings/sample -> ~5e-4).
//  3. float induction var (no I2F of r), float per-lane clamp (FMNMX),
//     floorf-based fraction (F2F.FLOOR+FSUB, shorter chain than F2I->I2F).
// Loop bounds stay warp-uniform ints; indexing stays plain int IMAD.
// ---------------------------------------------------------------------------

#define W    512
#define NT   180
#define PW   520                 // cells per row; 520*16B multiple of 128B
#define PH   520
#define NPIX (PW * PH)
#define PAD  4

__device__ uint4 g_padA[NPIX];   // normal orientation  (16B corner cells)
__device__ uint4 g_padB[NPIX];   // transposed orientation

typedef unsigned long long u64;

__device__ __forceinline__ u64 pk2(float lo, float hi) {
    u64 r; asm("mov.b64 %0, {%1, %2};" : "=l"(r) : "f"(lo), "f"(hi)); return r;
}
__device__ __forceinline__ void unpk2(u64 v, float& lo, float& hi) {
    asm("mov.b64 {%0, %1}, %2;" : "=f"(lo), "=f"(hi) : "l"(v));
}
__device__ __forceinline__ u64 fadd2(u64 a, u64 b) {
    u64 d; asm("add.rn.f32x2 %0, %1, %2;" : "=l"(d) : "l"(a), "l"(b)); return d;
}
__device__ __forceinline__ u64 h2f2(__half2 h) {         // half2 -> packed f32x2
    float2 f = __half22float2(h);
    return pk2(f.x, f.y);
}

// ---- fused build: z=0 -> padA (direct, coalesced), z=1 -> padB (transpose) --
__global__ __launch_bounds__(256) void build_pads(const float* __restrict__ x) {
    __shared__ float s[2][33][35];
    int tid = threadIdx.x;

    if (blockIdx.z == 0) {
        int idx = blockIdx.x * 256 + tid;
        if (idx >= NPIX) return;
        int ky = idx / PW;
        int kx = idx - ky * PW;
        int y  = ky - PAD;
        int x0 = kx - PAD;

        auto val = [&](int b, int r, int c) -> float {
            if ((unsigned)r < W && (unsigned)c < W)
                return x[b * (W * W) + r * W + c];
            return 0.0f;
        };
        __half2 h00 = __floats2half2_rn(val(0, y,     x0),     val(1, y,     x0));
        __half2 h01 = __floats2half2_rn(val(0, y,     x0 + 1), val(1, y,     x0 + 1));
        __half2 h10 = __floats2half2_rn(val(0, y + 1, x0),     val(1, y + 1, x0));
        __half2 h11 = __floats2half2_rn(val(0, y + 1, x0 + 1), val(1, y + 1, x0 + 1));
        uint4 cell;
        cell.x = *reinterpret_cast<uint32_t*>(&h00);
        cell.y = *reinterpret_cast<uint32_t*>(&h01);
        cell.z = *reinterpret_cast<uint32_t*>(&h10);
        cell.w = *reinterpret_cast<uint32_t*>(&h11);
        g_padA[idx] = cell;
    } else {
        const int TILES = (PW + 31) / 32;            // 17
        if (blockIdx.x >= TILES * TILES) return;
        int TX = (blockIdx.x % TILES) * 32;          // kx tile base (orig rows)
        int TY = (blockIdx.x / TILES) * 32;          // ky tile base (orig cols)
        int lane = tid & 31;
        int ty   = tid >> 5;

        for (int rr = ty; rr < 33; rr += 8) {
            int orow = TX - PAD + rr;
            for (int cc = lane; cc < 33; cc += 32) {
                int ocol = TY - PAD + cc;
                float v0 = 0.f, v1 = 0.f;
                if ((unsigned)orow < W && (unsigned)ocol < W) {
                    v0 = x[orow * W + ocol];
                    v1 = x[W * W + orow * W + ocol];
                }
                s[0][rr][cc] = v0;
                s[1][rr][cc] = v1;
            }
        }
        __syncthreads();

        int kx = TX + lane;
        if (kx >= PW) return;
        for (int j = ty; j < 32; j += 8) {
            int ky = TY + j;
            if (ky >= PH) continue;
            __half2 h00 = __floats2half2_rn(s[0][lane][j],         s[1][lane][j]);
            __half2 h01 = __floats2half2_rn(s[0][lane + 1][j],     s[1][lane + 1][j]);
            __half2 h10 = __floats2half2_rn(s[0][lane][j + 1],     s[1][lane][j + 1]);
            __half2 h11 = __floats2half2_rn(s[0][lane + 1][j + 1], s[1][lane + 1][j + 1]);
            uint4 cell;
            cell.x = *reinterpret_cast<uint32_t*>(&h00);
            cell.y = *reinterpret_cast<uint32_t*>(&h01);
            cell.z = *reinterpret_cast<uint32_t*>(&h10);
            cell.w = *reinterpret_cast<uint32_t*>(&h11);
            g_padB[ky * PW + kx] = cell;
        }
    }
}

// ---- main kernel ------------------------------------------------------------
__global__ __launch_bounds__(128) void radon_kernel(float* __restrict__ out) {
    __shared__ float2 red[4][32];

    int tid  = threadIdx.x;
    int lane = tid & 31;
    int wid  = tid >> 5;
    int t    = blockIdx.y;

    float th = (float)t * 0.017453292519943295f;
    float s  = sinf(th);                         // >= 0 for t in [0,180)
    float ct = cosf(th);
    float act = fabsf(ct);

    // shape + orientation selection (uniform per block)
    float bestc = 1e30f; int best_lw = 5; int best_tr = 0;
#pragma unroll
    for (int o = 0; o < 2; o++) {
        float a  = o ? act : s;
        float b  = o ? s   : act;
        float cx = o ? s   : act;
#pragma unroll
        for (int lw = 3; lw <= 5; lw++) {
            float wf = (float)(1 << lw);
            float hf = 32.0f / wf;
            float cost = (wf * a + hf * b + 2.0f) * (1.0f + wf * cx * (1.0f / 16.0f));
            if (cost < bestc) { bestc = cost; best_lw = lw; best_tr = o; }
        }
    }
    int lw     = best_lw;
    int w_     = 1 << lw;
    int h_     = 32 >> lw;
    int cgbits = 5 - lw;
    int cl  = lane & (w_ - 1);
    int rp  = lane >> lw;
    int col_group   = wid & ((1 << cgbits) - 1);
    int phase_group = wid >> cgbits;
    int phase   = phase_group * h_ + rp;         // 0..3
    int c_local = col_group * w_ + cl;           // 0..31
    int c = blockIdx.x * 32 + c_local;

    float base_c = (float)(2 * c + 1) * (1.0f / 512.0f) - 1.0f;
    float ix0 = fmaf(-255.5f, s,  fmaf( 256.0f * ct, base_c, 255.5f));
    float iy0 = fmaf(-255.5f, ct, fmaf(-256.0f * s,  base_c, 255.5f));

    // clip r to where (ix,iy) in [-1,512]^2; [rminf,rmaxf] always contains
    // 255.5 (perp distance to center < 256 = inscribed-circle radius)
    float sx  = fmaxf(s, 1e-8f);
    float sy  = (act < 1e-8f) ? ((ct < 0.f) ? -1e-8f : 1e-8f) : ct;
    float ivx = 1.0f / sx;
    float ivy = 1.0f / sy;
    float tx1 = (-1.0f  - ix0) * ivx;
    float tx2 = (512.0f - ix0) * ivx;
    float ty1 = (-1.0f  - iy0) * ivy;
    float ty2 = (512.0f - iy0) * ivy;
    float rminf = fmaxf(fmaxf(fminf(tx1, tx2), fminf(ty1, ty2)), 0.0f);
    float rmaxf = fminf(fminf(fmaxf(tx1, tx2), fmaxf(ty1, ty2)), 511.0f);
    int ra = (int)floorf(rminf);
    int rb = (int)ceilf(rmaxf);

    int ra_w = __reduce_min_sync(0xffffffffu, ra);
    int rb_w = __reduce_max_sync(0xffffffffu, rb);
    float ra1f = (float)(ra - 1);        // samples at ra-1 / rb+1 are EXACTLY 0
    float rb1f = (float)(rb + 1);

    float xc0, yc0, dxs, dys;
    const uint4* __restrict__ base;
    if (!best_tr) { xc0 = ix0 + (float)PAD; dxs = s;  yc0 = iy0 + (float)PAD; dys = ct; base = g_padA; }
    else          { xc0 = iy0 + (float)PAD; dxs = ct; yc0 = ix0 + (float)PAD; dys = s;  base = g_padB; }

    u64 acc0 = pk2(0.0f, 0.0f);
    u64 acc1 = pk2(0.0f, 0.0f);
    int toggle = 0;

    float rfi = (float)(ra_w + phase);   // exact float shadow of the counter
#pragma unroll 8
    for (int r = ra_w + phase; r <= rb_w; r += 4, rfi += 4.0f) {
        float rfc = fminf(fmaxf(rfi, ra1f), rb1f);   // per-lane clamp (zero cells)
        float px = fmaf(rfc, dxs, xc0);              // in [1, 519) by geometry+pad
        float py = fmaf(rfc, dys, yc0);
        float fpx = floorf(px);
        float fpy = floorf(py);
        float fx = px - fpx;
        float fy = py - fpy;
        int   x0 = (int)fpx;
        int   y0 = (int)fpy;

        uint4 cell = __ldg(base + (y0 * PW + x0));   // ONE LDG.128: all 4 corners

        __half2 v00 = *reinterpret_cast<__half2*>(&cell.x);
        __half2 v01 = *reinterpret_cast<__half2*>(&cell.y);
        __half2 v10 = *reinterpret_cast<__half2*>(&cell.z);
        __half2 v11 = *reinterpret_cast<__half2*>(&cell.w);

        __half2 fxh = __floats2half2_rn(fx, fx);
        __half2 fyh = __floats2half2_rn(fy, fy);
        __half2 l0h = __hfma2(fxh, __hsub2(v01, v00), v00);  // x-lerp row y0
        __half2 l1h = __hfma2(fxh, __hsub2(v11, v10), v10);  // x-lerp row y0+1
        __half2 vvh = __hfma2(fyh, __hsub2(l1h, l0h), l0h);  // y-lerp

        u64 vv = h2f2(vvh);
        if (toggle) acc1 = fadd2(acc1, vv); else acc0 = fadd2(acc0, vv);
        toggle ^= 1;
    }
    u64 acc = fadd2(acc0, acc1);

    float a0, a1;
    unpk2(acc, a0, a1);
    red[phase][c_local] = make_float2(a0, a1);
    __syncthreads();

    if (tid < 32) {
        float2 r0 = red[0][tid], r1 = red[1][tid], r2 = red[2][tid], r3 = red[3][tid];
        float sa = (r0.x + r1.x) + (r2.x + r3.x);
        float sb = (r0.y + r1.y) + (r2.y + r3.y);
        const float inv = 1.0f / 512.0f;
        int c2 = blockIdx.x * 32 + tid;
        int o0 = c2 * NT + t;
        out[o0]           = sa * inv;            // batch 0
        out[W * NT + o0]  = sb * inv;            // batch 1
    }
}

extern "C" void kernel_launch(void* const* d_in, const int* in_sizes, int n_in,
                              void* d_out, int out_size) {
    const float* x = (const float*)d_in[0];
    float* out = (float*)d_out;

    dim3 bgrid((NPIX + 255) / 256, 1, 2);        // z=0: padA, z=1: padB
    build_pads<<<bgrid, 256>>>(x);

    dim3 grid(W / 32, NT);
    radon_kernel<<<grid, 128>>>(out);
}

// round 12
// speedup vs baseline: 2.0734x; 1.0008x over previous
#include <cuda_runtime.h>
#include <cuda_fp16.h>
#include <cstdint>

// ---------------------------------------------------------------------------
// Radon transform, 180 angles, 512x512, batch 2 — round 12.
//
// R11 (82us, rel_err 4.70e-4) is the base. Single change this round:
// magic-number floor for the sample address path.
//   pbx = __fadd_rz(px, 2^23)  ->  bits(pbx) = 0x4B000000 + floor(px)
//   fx  = px - (pbx - 2^23)    (exact)
//   idx = bits(pby)*PW + bits(pbx) - KBIAS   (mod 2^32; bias cancels exactly)
// Deletes FLOOR(F2F) + F2I per coordinate (~40 cycles off the LDG address
// chain, -4 instructions). Values are bit-identical to R11's floorf path, so
// rel_err must stay EXACTLY 4.700945e-4 — that equality is the correctness
// check for the encoding.
// ---------------------------------------------------------------------------

#define W    512
#define NT   180
#define PW   520                 // cells per row; 520*16B multiple of 128B
#define PH   520
#define NPIX (PW * PH)
#define PAD  4
#define MAGIC 8388608.0f         // 2^23
#define KBIAS (0x4B000000u * (unsigned)(PW + 1))   // mod-2^32 wrap is intended

__device__ uint4 g_padA[NPIX];   // normal orientation  (16B corner cells)
__device__ uint4 g_padB[NPIX];   // transposed orientation

typedef unsigned long long u64;

__device__ __forceinline__ u64 pk2(float lo, float hi) {
    u64 r; asm("mov.b64 %0, {%1, %2};" : "=l"(r) : "f"(lo), "f"(hi)); return r;
}
__device__ __forceinline__ void unpk2(u64 v, float& lo, float& hi) {
    asm("mov.b64 {%0, %1}, %2;" : "=f"(lo), "=f"(hi) : "l"(v));
}
__device__ __forceinline__ u64 fadd2(u64 a, u64 b) {
    u64 d; asm("add.rn.f32x2 %0, %1, %2;" : "=l"(d) : "l"(a), "l"(b)); return d;
}
__device__ __forceinline__ u64 h2f2(__half2 h) {         // half2 -> packed f32x2
    float2 f = __half22float2(h);
    return pk2(f.x, f.y);
}

// ---- fused build: z=0 -> padA (direct, coalesced), z=1 -> padB (transpose) --
__global__ __launch_bounds__(256) void build_pads(const float* __restrict__ x) {
    __shared__ float s[2][33][35];
    int tid = threadIdx.x;

    if (blockIdx.z == 0) {
        int idx = blockIdx.x * 256 + tid;
        if (idx >= NPIX) return;
        int ky = idx / PW;
        int kx = idx - ky * PW;
        int y  = ky - PAD;
        int x0 = kx - PAD;

        auto val = [&](int b, int r, int c) -> float {
            if ((unsigned)r < W && (unsigned)c < W)
                return x[b * (W * W) + r * W + c];
            return 0.0f;
        };
        __half2 h00 = __floats2half2_rn(val(0, y,     x0),     val(1, y,     x0));
        __half2 h01 = __floats2half2_rn(val(0, y,     x0 + 1), val(1, y,     x0 + 1));
        __half2 h10 = __floats2half2_rn(val(0, y + 1, x0),     val(1, y + 1, x0));
        __half2 h11 = __floats2half2_rn(val(0, y + 1, x0 + 1), val(1, y + 1, x0 + 1));
        uint4 cell;
        cell.x = *reinterpret_cast<uint32_t*>(&h00);
        cell.y = *reinterpret_cast<uint32_t*>(&h01);
        cell.z = *reinterpret_cast<uint32_t*>(&h10);
        cell.w = *reinterpret_cast<uint32_t*>(&h11);
        g_padA[idx] = cell;
    } else {
        const int TILES = (PW + 31) / 32;            // 17
        if (blockIdx.x >= TILES * TILES) return;
        int TX = (blockIdx.x % TILES) * 32;          // kx tile base (orig rows)
        int TY = (blockIdx.x / TILES) * 32;          // ky tile base (orig cols)
        int lane = tid & 31;
        int ty   = tid >> 5;

        for (int rr = ty; rr < 33; rr += 8) {
            int orow = TX - PAD + rr;
            for (int cc = lane; cc < 33; cc += 32) {
                int ocol = TY - PAD + cc;
                float v0 = 0.f, v1 = 0.f;
                if ((unsigned)orow < W && (unsigned)ocol < W) {
                    v0 = x[orow * W + ocol];
                    v1 = x[W * W + orow * W + ocol];
                }
                s[0][rr][cc] = v0;
                s[1][rr][cc] = v1;
            }
        }
        __syncthreads();

        int kx = TX + lane;
        if (kx >= PW) return;
        for (int j = ty; j < 32; j += 8) {
            int ky = TY + j;
            if (ky >= PH) continue;
            __half2 h00 = __floats2half2_rn(s[0][lane][j],         s[1][lane][j]);
            __half2 h01 = __floats2half2_rn(s[0][lane + 1][j],     s[1][lane + 1][j]);
            __half2 h10 = __floats2half2_rn(s[0][lane][j + 1],     s[1][lane][j + 1]);
            __half2 h11 = __floats2half2_rn(s[0][lane + 1][j + 1], s[1][lane + 1][j + 1]);
            uint4 cell;
            cell.x = *reinterpret_cast<uint32_t*>(&h00);
            cell.y = *reinterpret_cast<uint32_t*>(&h01);
            cell.z = *reinterpret_cast<uint32_t*>(&h10);
            cell.w = *reinterpret_cast<uint32_t*>(&h11);
            g_padB[ky * PW + kx] = cell;
        }
    }
}

// ---- main kernel ------------------------------------------------------------
__global__ __launch_bounds__(128) void radon_kernel(float* __restrict__ out) {
    __shared__ float2 red[4][32];

    int tid  = threadIdx.x;
    int lane = tid & 31;
    int wid  = tid >> 5;
    int t    = blockIdx.y;

    float th = (float)t * 0.017453292519943295f;
    float s  = sinf(th);                         // >= 0 for t in [0,180)
    float ct = cosf(th);
    float act = fabsf(ct);

    // shape + orientation selection (uniform per block)
    float bestc = 1e30f; int best_lw = 5; int best_tr = 0;
#pragma unroll
    for (int o = 0; o < 2; o++) {
        float a  = o ? act : s;
        float b  = o ? s   : act;
        float cx = o ? s   : act;
#pragma unroll
        for (int lw = 3; lw <= 5; lw++) {
            float wf = (float)(1 << lw);
            float hf = 32.0f / wf;
            float cost = (wf * a + hf * b + 2.0f) * (1.0f + wf * cx * (1.0f / 16.0f));
            if (cost < bestc) { bestc = cost; best_lw = lw; best_tr = o; }
        }
    }
    int lw     = best_lw;
    int w_     = 1 << lw;
    int h_     = 32 >> lw;
    int cgbits = 5 - lw;
    int cl  = lane & (w_ - 1);
    int rp  = lane >> lw;
    int col_group   = wid & ((1 << cgbits) - 1);
    int phase_group = wid >> cgbits;
    int phase   = phase_group * h_ + rp;         // 0..3
    int c_local = col_group * w_ + cl;           // 0..31
    int c = blockIdx.x * 32 + c_local;

    float base_c = (float)(2 * c + 1) * (1.0f / 512.0f) - 1.0f;
    float ix0 = fmaf(-255.5f, s,  fmaf( 256.0f * ct, base_c, 255.5f));
    float iy0 = fmaf(-255.5f, ct, fmaf(-256.0f * s,  base_c, 255.5f));

    // clip r to where (ix,iy) in [-1,512]^2; [rminf,rmaxf] always contains
    // 255.5 (perp distance to center < 256 = inscribed-circle radius)
    float sx  = fmaxf(s, 1e-8f);
    float sy  = (act < 1e-8f) ? ((ct < 0.f) ? -1e-8f : 1e-8f) : ct;
    float ivx = 1.0f / sx;
    float ivy = 1.0f / sy;
    float tx1 = (-1.0f  - ix0) * ivx;
    float tx2 = (512.0f - ix0) * ivx;
    float ty1 = (-1.0f  - iy0) * ivy;
    float ty2 = (512.0f - iy0) * ivy;
    float rminf = fmaxf(fmaxf(fminf(tx1, tx2), fminf(ty1, ty2)), 0.0f);
    float rmaxf = fminf(fminf(fmaxf(tx1, tx2), fmaxf(ty1, ty2)), 511.0f);
    int ra = (int)floorf(rminf);
    int rb = (int)ceilf(rmaxf);

    int ra_w = __reduce_min_sync(0xffffffffu, ra);
    int rb_w = __reduce_max_sync(0xffffffffu, rb);
    float ra1f = (float)(ra - 1);        // samples at ra-1 / rb+1 are EXACTLY 0
    float rb1f = (float)(rb + 1);

    float xc0, yc0, dxs, dys;
    const uint4* __restrict__ base;
    if (!best_tr) { xc0 = ix0 + (float)PAD; dxs = s;  yc0 = iy0 + (float)PAD; dys = ct; base = g_padA; }
    else          { xc0 = iy0 + (float)PAD; dxs = ct; yc0 = ix0 + (float)PAD; dys = s;  base = g_padB; }

    u64 acc0 = pk2(0.0f, 0.0f);
    u64 acc1 = pk2(0.0f, 0.0f);
    int toggle = 0;

    float rfi = (float)(ra_w + phase);   // exact float shadow of the counter
#pragma unroll 8
    for (int r = ra_w + phase; r <= rb_w; r += 4, rfi += 4.0f) {
        float rfc = fminf(fmaxf(rfi, ra1f), rb1f);   // per-lane clamp (zero cells)
        float px = fmaf(rfc, dxs, xc0);              // in [1, 519) by geometry+pad
        float py = fmaf(rfc, dys, yc0);

        float pbx = __fadd_rz(px, MAGIC);            // bits = 0x4B000000 + floor(px)
        float pby = __fadd_rz(py, MAGIC);
        float fx = px - (pbx - MAGIC);               // exact fraction
        float fy = py - (pby - MAGIC);
        uint32_t idx = __float_as_uint(pby) * (unsigned)PW
                     + __float_as_uint(pbx) - KBIAS; // = y0*PW + x0 (mod 2^32)

        uint4 cell = __ldg(base + idx);              // ONE LDG.128: all 4 corners

        __half2 v00 = *reinterpret_cast<__half2*>(&cell.x);
        __half2 v01 = *reinterpret_cast<__half2*>(&cell.y);
        __half2 v10 = *reinterpret_cast<__half2*>(&cell.z);
        __half2 v11 = *reinterpret_cast<__half2*>(&cell.w);

        __half2 fxh = __floats2half2_rn(fx, fx);
        __half2 fyh = __floats2half2_rn(fy, fy);
        __half2 l0h = __hfma2(fxh, __hsub2(v01, v00), v00);  // x-lerp row y0
        __half2 l1h = __hfma2(fxh, __hsub2(v11, v10), v10);  // x-lerp row y0+1
        __half2 vvh = __hfma2(fyh, __hsub2(l1h, l0h), l0h);  // y-lerp

        u64 vv = h2f2(vvh);
        if (toggle) acc1 = fadd2(acc1, vv); else acc0 = fadd2(acc0, vv);
        toggle ^= 1;
    }
    u64 acc = fadd2(acc0, acc1);

    float a0, a1;
    unpk2(acc, a0, a1);
    red[phase][c_local] = make_float2(a0, a1);
    __syncthreads();

    if (tid < 32) {
        float2 r0 = red[0][tid], r1 = red[1][tid], r2 = red[2][tid], r3 = red[3][tid];
        float sa = (r0.x + r1.x) + (r2.x + r3.x);
        float sb = (r0.y + r1.y) + (r2.y + r3.y);
        const float inv = 1.0f / 512.0f;
        int c2 = blockIdx.x * 32 + tid;
        int o0 = c2 * NT + t;
        out[o0]           = sa * inv;            // batch 0
        out[W * NT + o0]  = sb * inv;            // batch 1
    }
}

extern "C" void kernel_launch(void* const* d_in, const int* in_sizes, int n_in,
                              void* d_out, int out_size) {
    const float* x = (const float*)d_in[0];
    float* out = (float*)d_out;

    dim3 bgrid((NPIX + 255) / 256, 1, 2);        // z=0: padA, z=1: padB
    build_pads<<<bgrid, 256>>>(x);

    dim3 grid(W / 32, NT);
    radon_kernel<<<grid, 128>>>(out);
}

// round 13
// speedup vs baseline: 2.0742x; 1.0004x over previous
#include <cuda_runtime.h>
#include <cuda_fp16.h>
#include <cstdint>

// ---------------------------------------------------------------------------
// Radon transform, 180 angles, 512x512, batch 2 — round 13.
//
// R12 proved the magic-floor path exact (rel_err bit-identical). Profile says
// no pipe saturated (issue 56, L1 67) -> the gap is wave/tail structure:
// 2880 x 4 warps = 78 warps/SM > 64 capacity = 2 ragged waves.
//
// R13: 64-thread blocks (2 warps, 2 r-phases). 5760 warps = 38.9/SM ->
// SINGLE WAVE, no tail; per-SM load averages ~19 blocks. Everything else
// (fp16 corner cells, dual orientation, magic floor, clamp-to-zero-cells)
// unchanged.
// ---------------------------------------------------------------------------

#define W    512
#define NT   180
#define PW   520                 // cells per row; 520*16B multiple of 128B
#define PH   520
#define NPIX (PW * PH)
#define PAD  4
#define MAGIC 8388608.0f         // 2^23
#define KBIAS (0x4B000000u * (unsigned)(PW + 1))   // mod-2^32 wrap is intended

__device__ uint4 g_padA[NPIX];   // normal orientation  (16B corner cells)
__device__ uint4 g_padB[NPIX];   // transposed orientation

typedef unsigned long long u64;

__device__ __forceinline__ u64 pk2(float lo, float hi) {
    u64 r; asm("mov.b64 %0, {%1, %2};" : "=l"(r) : "f"(lo), "f"(hi)); return r;
}
__device__ __forceinline__ void unpk2(u64 v, float& lo, float& hi) {
    asm("mov.b64 {%0, %1}, %2;" : "=f"(lo), "=f"(hi) : "l"(v));
}
__device__ __forceinline__ u64 fadd2(u64 a, u64 b) {
    u64 d; asm("add.rn.f32x2 %0, %1, %2;" : "=l"(d) : "l"(a), "l"(b)); return d;
}
__device__ __forceinline__ u64 h2f2(__half2 h) {         // half2 -> packed f32x2
    float2 f = __half22float2(h);
    return pk2(f.x, f.y);
}

// ---- fused build: z=0 -> padA (direct, coalesced), z=1 -> padB (transpose) --
__global__ __launch_bounds__(256) void build_pads(const float* __restrict__ x) {
    __shared__ float s[2][33][35];
    int tid = threadIdx.x;

    if (blockIdx.z == 0) {
        int idx = blockIdx.x * 256 + tid;
        if (idx >= NPIX) return;
        int ky = idx / PW;
        int kx = idx - ky * PW;
        int y  = ky - PAD;
        int x0 = kx - PAD;

        auto val = [&](int b, int r, int c) -> float {
            if ((unsigned)r < W && (unsigned)c < W)
                return x[b * (W * W) + r * W + c];
            return 0.0f;
        };
        __half2 h00 = __floats2half2_rn(val(0, y,     x0),     val(1, y,     x0));
        __half2 h01 = __floats2half2_rn(val(0, y,     x0 + 1), val(1, y,     x0 + 1));
        __half2 h10 = __floats2half2_rn(val(0, y + 1, x0),     val(1, y + 1, x0));
        __half2 h11 = __floats2half2_rn(val(0, y + 1, x0 + 1), val(1, y + 1, x0 + 1));
        uint4 cell;
        cell.x = *reinterpret_cast<uint32_t*>(&h00);
        cell.y = *reinterpret_cast<uint32_t*>(&h01);
        cell.z = *reinterpret_cast<uint32_t*>(&h10);
        cell.w = *reinterpret_cast<uint32_t*>(&h11);
        g_padA[idx] = cell;
    } else {
        const int TILES = (PW + 31) / 32;            // 17
        if (blockIdx.x >= TILES * TILES) return;
        int TX = (blockIdx.x % TILES) * 32;          // kx tile base (orig rows)
        int TY = (blockIdx.x / TILES) * 32;          // ky tile base (orig cols)
        int lane = tid & 31;
        int ty   = tid >> 5;

        for (int rr = ty; rr < 33; rr += 8) {
            int orow = TX - PAD + rr;
            for (int cc = lane; cc < 33; cc += 32) {
                int ocol = TY - PAD + cc;
                float v0 = 0.f, v1 = 0.f;
                if ((unsigned)orow < W && (unsigned)ocol < W) {
                    v0 = x[orow * W + ocol];
                    v1 = x[W * W + orow * W + ocol];
                }
                s[0][rr][cc] = v0;
                s[1][rr][cc] = v1;
            }
        }
        __syncthreads();

        int kx = TX + lane;
        if (kx >= PW) return;
        for (int j = ty; j < 32; j += 8) {
            int ky = TY + j;
            if (ky >= PH) continue;
            __half2 h00 = __floats2half2_rn(s[0][lane][j],         s[1][lane][j]);
            __half2 h01 = __floats2half2_rn(s[0][lane + 1][j],     s[1][lane + 1][j]);
            __half2 h10 = __floats2half2_rn(s[0][lane][j + 1],     s[1][lane][j + 1]);
            __half2 h11 = __floats2half2_rn(s[0][lane + 1][j + 1], s[1][lane + 1][j + 1]);
            uint4 cell;
            cell.x = *reinterpret_cast<uint32_t*>(&h00);
            cell.y = *reinterpret_cast<uint32_t*>(&h01);
            cell.z = *reinterpret_cast<uint32_t*>(&h10);
            cell.w = *reinterpret_cast<uint32_t*>(&h11);
            g_padB[ky * PW + kx] = cell;
        }
    }
}

// ---- main kernel: 64 threads = 32 columns x 2 r-phases ----------------------
__global__ __launch_bounds__(64) void radon_kernel(float* __restrict__ out) {
    __shared__ float2 red[2][32];

    int tid  = threadIdx.x;
    int lane = tid & 31;
    int wid  = tid >> 5;                         // 0..1
    int t    = blockIdx.y;

    float th = (float)t * 0.017453292519943295f;
    float s  = sinf(th);                         // >= 0 for t in [0,180)
    float ct = cosf(th);
    float act = fabsf(ct);

    // shape + orientation selection (uniform per block); warp footprint is
    // w_ columns x h_ phases with w_*h_ = 32, w_ in {16, 32}.
    float bestc = 1e30f; int best_lw = 5; int best_tr = 0;
#pragma unroll
    for (int o = 0; o < 2; o++) {
        float a  = o ? act : s;
        float b  = o ? s   : act;
        float cx = o ? s   : act;
#pragma unroll
        for (int lw = 4; lw <= 5; lw++) {
            float wf = (float)(1 << lw);
            float hf = 32.0f / wf;
            float cost = (wf * a + hf * b + 2.0f) * (1.0f + wf * cx * (1.0f / 16.0f));
            if (cost < bestc) { bestc = cost; best_lw = lw; best_tr = o; }
        }
    }
    int lw     = best_lw;
    int w_     = 1 << lw;
    int h_     = 32 >> lw;                       // phases per warp (1 or 2)
    int cgbits = 5 - lw;
    int cl  = lane & (w_ - 1);
    int rp  = lane >> lw;
    int col_group   = wid & ((1 << cgbits) - 1);
    int phase_group = wid >> cgbits;
    int phase   = phase_group * h_ + rp;         // 0..1
    int c_local = col_group * w_ + cl;           // 0..31
    int c = blockIdx.x * 32 + c_local;

    float base_c = (float)(2 * c + 1) * (1.0f / 512.0f) - 1.0f;
    float ix0 = fmaf(-255.5f, s,  fmaf( 256.0f * ct, base_c, 255.5f));
    float iy0 = fmaf(-255.5f, ct, fmaf(-256.0f * s,  base_c, 255.5f));

    // clip r to where (ix,iy) in [-1,512]^2
    float sx  = fmaxf(s, 1e-8f);
    float sy  = (act < 1e-8f) ? ((ct < 0.f) ? -1e-8f : 1e-8f) : ct;
    float ivx = 1.0f / sx;
    float ivy = 1.0f / sy;
    float tx1 = (-1.0f  - ix0) * ivx;
    float tx2 = (512.0f - ix0) * ivx;
    float ty1 = (-1.0f  - iy0) * ivy;
    float ty2 = (512.0f - iy0) * ivy;
    float rminf = fmaxf(fmaxf(fminf(tx1, tx2), fminf(ty1, ty2)), 0.0f);
    float rmaxf = fminf(fminf(fmaxf(tx1, tx2), fmaxf(ty1, ty2)), 511.0f);
    int ra = (int)floorf(rminf);
    int rb = (int)ceilf(rmaxf);

    int ra_w = __reduce_min_sync(0xffffffffu, ra);
    int rb_w = __reduce_max_sync(0xffffffffu, rb);
    float ra1f = (float)(ra - 1);        // samples at ra-1 / rb+1 are EXACTLY 0
    float rb1f = (float)(rb + 1);

    float xc0, yc0, dxs, dys;
    const uint4* __restrict__ base;
    if (!best_tr) { xc0 = ix0 + (float)PAD; dxs = s;  yc0 = iy0 + (float)PAD; dys = ct; base = g_padA; }
    else          { xc0 = iy0 + (float)PAD; dxs = ct; yc0 = ix0 + (float)PAD; dys = s;  base = g_padB; }

    u64 acc0 = pk2(0.0f, 0.0f);
    u64 acc1 = pk2(0.0f, 0.0f);
    int toggle = 0;

    float rfi = (float)(ra_w + phase);   // exact float shadow of the counter
#pragma unroll 8
    for (int r = ra_w + phase; r <= rb_w; r += 2, rfi += 2.0f) {
        float rfc = fminf(fmaxf(rfi, ra1f), rb1f);   // per-lane clamp (zero cells)
        float px = fmaf(rfc, dxs, xc0);              // in [1, 519) by geometry+pad
        float py = fmaf(rfc, dys, yc0);

        float pbx = __fadd_rz(px, MAGIC);            // bits = 0x4B000000 + floor(px)
        float pby = __fadd_rz(py, MAGIC);
        float fx = px - (pbx - MAGIC);               // exact fraction
        float fy = py - (pby - MAGIC);
        uint32_t idx = __float_as_uint(pby) * (unsigned)PW
                     + __float_as_uint(pbx) - KBIAS; // = y0*PW + x0 (mod 2^32)

        uint4 cell = __ldg(base + idx);              // ONE LDG.128: all 4 corners

        __half2 v00 = *reinterpret_cast<__half2*>(&cell.x);
        __half2 v01 = *reinterpret_cast<__half2*>(&cell.y);
        __half2 v10 = *reinterpret_cast<__half2*>(&cell.z);
        __half2 v11 = *reinterpret_cast<__half2*>(&cell.w);

        __half2 fxh = __floats2half2_rn(fx, fx);
        __half2 fyh = __floats2half2_rn(fy, fy);
        __half2 l0h = __hfma2(fxh, __hsub2(v01, v00), v00);  // x-lerp row y0
        __half2 l1h = __hfma2(fxh, __hsub2(v11, v10), v10);  // x-lerp row y0+1
        __half2 vvh = __hfma2(fyh, __hsub2(l1h, l0h), l0h);  // y-lerp

        u64 vv = h2f2(vvh);
        if (toggle) acc1 = fadd2(acc1, vv); else acc0 = fadd2(acc0, vv);
        toggle ^= 1;
    }
    u64 acc = fadd2(acc0, acc1);

    float a0, a1;
    unpk2(acc, a0, a1);
    red[phase][c_local] = make_float2(a0, a1);
    __syncthreads();

    if (tid < 32) {
        float2 r0 = red[0][tid], r1 = red[1][tid];
        float sa = r0.x + r1.x;
        float sb = r0.y + r1.y;
        const float inv = 1.0f / 512.0f;
        int c2 = blockIdx.x * 32 + tid;
        int o0 = c2 * NT + t;
        out[o0]           = sa * inv;            // batch 0
        out[W * NT + o0]  = sb * inv;            // batch 1
    }
}

extern "C" void kernel_launch(void* const* d_in, const int* in_sizes, int n_in,
                              void* d_out, int out_size) {
    const float* x = (const float*)d_in[0];
    float* out = (float*)d_out;

    dim3 bgrid((NPIX + 255) / 256, 1, 2);        // z=0: padA, z=1: padB
    build_pads<<<bgrid, 256>>>(x);

    dim3 grid(W / 32, NT);
    radon_kernel<<<grid, 64>>>(out);
}

// round 14
// speedup vs baseline: 2.1129x; 1.0187x over previous
#include <cuda_runtime.h>
#include <cuda_fp16.h>
#include <cstdint>

// ---------------------------------------------------------------------------
// Radon transform, 180 angles, 512x512, batch 2 — round 14.
//
// R13 falsified the wave-structure theory (64-thr blocks: occ down, same wall).
// Base = R12 (128 threads, fp16 corner cells, magic floor; radon 78.7us,
// issue 55.7%). R14 single change: split the r-loop into
//   head (clamped) | body (NO clamp: all lanes in-range) | tail (clamped)
// using warp-uniform boundaries max(ra)/min(rb). Body = ~85-90% of iters,
// saves 2 FMNMX/iter + 4 cycles of address chain. Bit-identical math:
// rel_err must stay EXACTLY 4.700945e-4.
// ---------------------------------------------------------------------------

#define W    512
#define NT   180
#define PW   520                 // cells per row; 520*16B multiple of 128B
#define PH   520
#define NPIX (PW * PH)
#define PAD  4
#define MAGIC 8388608.0f         // 2^23
#define KBIAS (0x4B000000u * (unsigned)(PW + 1))   // mod-2^32 wrap is intended

__device__ uint4 g_padA[NPIX];   // normal orientation  (16B corner cells)
__device__ uint4 g_padB[NPIX];   // transposed orientation

typedef unsigned long long u64;

__device__ __forceinline__ u64 pk2(float lo, float hi) {
    u64 r; asm("mov.b64 %0, {%1, %2};" : "=l"(r) : "f"(lo), "f"(hi)); return r;
}
__device__ __forceinline__ void unpk2(u64 v, float& lo, float& hi) {
    asm("mov.b64 {%0, %1}, %2;" : "=f"(lo), "=f"(hi) : "l"(v));
}
__device__ __forceinline__ u64 fadd2(u64 a, u64 b) {
    u64 d; asm("add.rn.f32x2 %0, %1, %2;" : "=l"(d) : "l"(a), "l"(b)); return d;
}
__device__ __forceinline__ u64 h2f2(__half2 h) {         // half2 -> packed f32x2
    float2 f = __half22float2(h);
    return pk2(f.x, f.y);
}

// ---- fused build: z=0 -> padA (direct, coalesced), z=1 -> padB (transpose) --
__global__ __launch_bounds__(256) void build_pads(const float* __restrict__ x) {
    __shared__ float s[2][33][35];
    int tid = threadIdx.x;

    if (blockIdx.z == 0) {
        int idx = blockIdx.x * 256 + tid;
        if (idx >= NPIX) return;
        int ky = idx / PW;
        int kx = idx - ky * PW;
        int y  = ky - PAD;
        int x0 = kx - PAD;

        auto val = [&](int b, int r, int c) -> float {
            if ((unsigned)r < W && (unsigned)c < W)
                return x[b * (W * W) + r * W + c];
            return 0.0f;
        };
        __half2 h00 = __floats2half2_rn(val(0, y,     x0),     val(1, y,     x0));
        __half2 h01 = __floats2half2_rn(val(0, y,     x0 + 1), val(1, y,     x0 + 1));
        __half2 h10 = __floats2half2_rn(val(0, y + 1, x0),     val(1, y + 1, x0));
        __half2 h11 = __floats2half2_rn(val(0, y + 1, x0 + 1), val(1, y + 1, x0 + 1));
        uint4 cell;
        cell.x = *reinterpret_cast<uint32_t*>(&h00);
        cell.y = *reinterpret_cast<uint32_t*>(&h01);
        cell.z = *reinterpret_cast<uint32_t*>(&h10);
        cell.w = *reinterpret_cast<uint32_t*>(&h11);
        g_padA[idx] = cell;
    } else {
        const int TILES = (PW + 31) / 32;            // 17
        if (blockIdx.x >= TILES * TILES) return;
        int TX = (blockIdx.x % TILES) * 32;          // kx tile base (orig rows)
        int TY = (blockIdx.x / TILES) * 32;          // ky tile base (orig cols)
        int lane = tid & 31;
        int ty   = tid >> 5;

        for (int rr = ty; rr < 33; rr += 8) {
            int orow = TX - PAD + rr;
            for (int cc = lane; cc < 33; cc += 32) {
                int ocol = TY - PAD + cc;
                float v0 = 0.f, v1 = 0.f;
                if ((unsigned)orow < W && (unsigned)ocol < W) {
                    v0 = x[orow * W + ocol];
                    v1 = x[W * W + orow * W + ocol];
                }
                s[0][rr][cc] = v0;
                s[1][rr][cc] = v1;
            }
        }
        __syncthreads();

        int kx = TX + lane;
        if (kx >= PW) return;
        for (int j = ty; j < 32; j += 8) {
            int ky = TY + j;
            if (ky >= PH) continue;
            __half2 h00 = __floats2half2_rn(s[0][lane][j],         s[1][lane][j]);
            __half2 h01 = __floats2half2_rn(s[0][lane + 1][j],     s[1][lane + 1][j]);
            __half2 h10 = __floats2half2_rn(s[0][lane][j + 1],     s[1][lane][j + 1]);
            __half2 h11 = __floats2half2_rn(s[0][lane + 1][j + 1], s[1][lane + 1][j + 1]);
            uint4 cell;
            cell.x = *reinterpret_cast<uint32_t*>(&h00);
            cell.y = *reinterpret_cast<uint32_t*>(&h01);
            cell.z = *reinterpret_cast<uint32_t*>(&h10);
            cell.w = *reinterpret_cast<uint32_t*>(&h11);
            g_padB[ky * PW + kx] = cell;
        }
    }
}

// ---- main kernel: 128 threads = 32 columns x 4 r-phases ---------------------
__global__ __launch_bounds__(128) void radon_kernel(float* __restrict__ out) {
    __shared__ float2 red[4][32];

    int tid  = threadIdx.x;
    int lane = tid & 31;
    int wid  = tid >> 5;
    int t    = blockIdx.y;

    float th = (float)t * 0.017453292519943295f;
    float s  = sinf(th);                         // >= 0 for t in [0,180)
    float ct = cosf(th);
    float act = fabsf(ct);

    // shape + orientation selection (uniform per block)
    float bestc = 1e30f; int best_lw = 5; int best_tr = 0;
#pragma unroll
    for (int o = 0; o < 2; o++) {
        float a  = o ? act : s;
        float b  = o ? s   : act;
        float cx = o ? s   : act;
#pragma unroll
        for (int lw = 3; lw <= 5; lw++) {
            float wf = (float)(1 << lw);
            float hf = 32.0f / wf;
            float cost = (wf * a + hf * b + 2.0f) * (1.0f + wf * cx * (1.0f / 16.0f));
            if (cost < bestc) { bestc = cost; best_lw = lw; best_tr = o; }
        }
    }
    int lw     = best_lw;
    int w_     = 1 << lw;
    int h_     = 32 >> lw;
    int cgbits = 5 - lw;
    int cl  = lane & (w_ - 1);
    int rp  = lane >> lw;
    int col_group   = wid & ((1 << cgbits) - 1);
    int phase_group = wid >> cgbits;
    int phase   = phase_group * h_ + rp;         // 0..3
    int c_local = col_group * w_ + cl;           // 0..31
    int c = blockIdx.x * 32 + c_local;

    float base_c = (float)(2 * c + 1) * (1.0f / 512.0f) - 1.0f;
    float ix0 = fmaf(-255.5f, s,  fmaf( 256.0f * ct, base_c, 255.5f));
    float iy0 = fmaf(-255.5f, ct, fmaf(-256.0f * s,  base_c, 255.5f));

    // clip r to where (ix,iy) in [-1,512]^2
    float sx  = fmaxf(s, 1e-8f);
    float sy  = (act < 1e-8f) ? ((ct < 0.f) ? -1e-8f : 1e-8f) : ct;
    float ivx = 1.0f / sx;
    float ivy = 1.0f / sy;
    float tx1 = (-1.0f  - ix0) * ivx;
    float tx2 = (512.0f - ix0) * ivx;
    float ty1 = (-1.0f  - iy0) * ivy;
    float ty2 = (512.0f - iy0) * ivy;
    float rminf = fmaxf(fmaxf(fminf(tx1, tx2), fminf(ty1, ty2)), 0.0f);
    float rmaxf = fminf(fminf(fmaxf(tx1, tx2), fmaxf(ty1, ty2)), 511.0f);
    int ra = (int)floorf(rminf);
    int rb = (int)ceilf(rmaxf);

    int ra_w  = __reduce_min_sync(0xffffffffu, ra);   // warp outer bounds
    int rb_w  = __reduce_max_sync(0xffffffffu, rb);
    int ra_hi = __reduce_max_sync(0xffffffffu, ra);   // interior (all-lanes-valid)
    int rb_lo = __reduce_min_sync(0xffffffffu, rb);
    float ra1f = (float)(ra - 1);        // samples at ra-1 / rb+1 are EXACTLY 0
    float rb1f = (float)(rb + 1);

    float xc0, yc0, dxs, dys;
    const uint4* __restrict__ base;
    if (!best_tr) { xc0 = ix0 + (float)PAD; dxs = s;  yc0 = iy0 + (float)PAD; dys = ct; base = g_padA; }
    else          { xc0 = iy0 + (float)PAD; dxs = ct; yc0 = ix0 + (float)PAD; dys = s;  base = g_padB; }

    u64 acc0 = pk2(0.0f, 0.0f);
    u64 acc1 = pk2(0.0f, 0.0f);
    int toggle = 0;

    auto do_sample = [&](float rfc) {
        float px = fmaf(rfc, dxs, xc0);              // in [1, 519) by geometry+pad
        float py = fmaf(rfc, dys, yc0);
        float pbx = __fadd_rz(px, MAGIC);            // bits = 0x4B000000 + floor(px)
        float pby = __fadd_rz(py, MAGIC);
        float fx = px - (pbx - MAGIC);               // exact fraction
        float fy = py - (pby - MAGIC);
        uint32_t idx = __float_as_uint(pby) * (unsigned)PW
                     + __float_as_uint(pbx) - KBIAS; // = y0*PW + x0 (mod 2^32)

        uint4 cell = __ldg(base + idx);              // ONE LDG.128: all 4 corners

        __half2 v00 = *reinterpret_cast<__half2*>(&cell.x);
        __half2 v01 = *reinterpret_cast<__half2*>(&cell.y);
        __half2 v10 = *reinterpret_cast<__half2*>(&cell.z);
        __half2 v11 = *reinterpret_cast<__half2*>(&cell.w);

        __half2 fxh = __floats2half2_rn(fx, fx);
        __half2 fyh = __floats2half2_rn(fy, fy);
        __half2 l0h = __hfma2(fxh, __hsub2(v01, v00), v00);  // x-lerp row y0
        __half2 l1h = __hfma2(fxh, __hsub2(v11, v10), v10);  // x-lerp row y0+1
        __half2 vvh = __hfma2(fyh, __hsub2(l1h, l0h), l0h);  // y-lerp

        u64 vv = h2f2(vvh);
        if (toggle) acc1 = fadd2(acc1, vv); else acc0 = fadd2(acc0, vv);
        toggle ^= 1;
    };

    int   r   = ra_w + phase;
    float rfi = (float)r;                // exact float shadow of the counter

    // HEAD: some lanes below their own range -> clamp to zero cells
    for (; r < ra_hi; r += 4, rfi += 4.0f)
        do_sample(fminf(fmaxf(rfi, ra1f), rb1f));

    // BODY: every lane in-range -> no clamp (bit-identical: clamp was no-op)
#pragma unroll 8
    for (; r <= rb_lo; r += 4, rfi += 4.0f)
        do_sample(rfi);

    // TAIL: some lanes past their own range -> clamp to zero cells
    for (; r <= rb_w; r += 4, rfi += 4.0f)
        do_sample(fminf(fmaxf(rfi, ra1f), rb1f));

    u64 acc = fadd2(acc0, acc1);

    float a0, a1;
    unpk2(acc, a0, a1);
    red[phase][c_local] = make_float2(a0, a1);
    __syncthreads();

    if (tid < 32) {
        float2 r0 = red[0][tid], r1 = red[1][tid], r2 = red[2][tid], r3 = red[3][tid];
        float sa = (r0.x + r1.x) + (r2.x + r3.x);
        float sb = (r0.y + r1.y) + (r2.y + r3.y);
        const float inv = 1.0f / 512.0f;
        int c2 = blockIdx.x * 32 + tid;
        int o0 = c2 * NT + t;
        out[o0]           = sa * inv;            // batch 0
        out[W * NT + o0]  = sb * inv;            // batch 1
    }
}

extern "C" void kernel_launch(void* const* d_in, const int* in_sizes, int n_in,
                              void* d_out, int out_size) {
    const float* x = (const float*)d_in[0];
    float* out = (float*)d_out;

    dim3 bgrid((NPIX + 255) / 256, 1, 2);        // z=0: padA, z=1: padB
    build_pads<<<bgrid, 256>>>(x);

    dim3 grid(W / 32, NT);
    radon_kernel<<<grid, 128>>>(out);
}